// round 1
// baseline (speedup 1.0000x reference)
#include <cuda_runtime.h>
#include <cstddef>

namespace {

constexpr int B = 2, N = 512, C = 64, H = 8;
constexpr int TC = 2 * C;          // 128 combined channels (q then k)
constexpr int THREADS = 256;

__global__ __launch_bounds__(THREADS, 2)
void mha_fused_kernel(const float* __restrict__ q,
                      const float* __restrict__ k,
                      const float* __restrict__ roi,
                      const float* __restrict__ W,
                      const float* __restrict__ bias,
                      float* __restrict__ out)
{
    // W transposed to [c][h] so each c gives two float4 broadcast loads (h=0..3, h=4..7)
    __shared__ float Ws[TC * H];       // 4 KB
    __shared__ float wsum[8][H];       // per-warp partial sums
    __shared__ float bsh[H];

    const int tid = threadIdx.x;
    const int bm  = blockIdx.x;        // b*N + m

    // Transpose W[h][2C] -> Ws[c][h]
    for (int i = tid; i < TC * H; i += THREADS) {
        const int h = i >> 7;          // i / 128
        const int c = i & 127;         // i % 128
        Ws[c * H + h] = W[i];
    }
    if (tid < H) bsh[tid] = bias[tid];
    __syncthreads();

    const float* qbase = q + (size_t)bm * N * C;
    const float* kbase = k + (size_t)bm * N * C;

    float attn[2][H];
    float sums[H];
#pragma unroll
    for (int h = 0; h < H; ++h) sums[h] = 0.f;

#pragma unroll
    for (int j = 0; j < 2; ++j) {
        const int n = tid + j * THREADS;
        const float4* q4 = reinterpret_cast<const float4*>(qbase + (size_t)n * C);
        const float4* k4 = reinterpret_cast<const float4*>(kbase + (size_t)n * C);

        float acc[H];
#pragma unroll
        for (int h = 0; h < H; ++h) acc[h] = bsh[h];

        // ---- query projection: c in [0, 64) ----
#pragma unroll
        for (int cb = 0; cb < C / 4; ++cb) {
            const float4 v = q4[cb];
            const float4* wp = reinterpret_cast<const float4*>(&Ws[(cb * 4) * H]);
            const float vc[4] = {v.x, v.y, v.z, v.w};
#pragma unroll
            for (int c = 0; c < 4; ++c) {
                const float4 w0 = wp[c * 2 + 0];
                const float4 w1 = wp[c * 2 + 1];
                acc[0] = fmaf(vc[c], w0.x, acc[0]);
                acc[1] = fmaf(vc[c], w0.y, acc[1]);
                acc[2] = fmaf(vc[c], w0.z, acc[2]);
                acc[3] = fmaf(vc[c], w0.w, acc[3]);
                acc[4] = fmaf(vc[c], w1.x, acc[4]);
                acc[5] = fmaf(vc[c], w1.y, acc[5]);
                acc[6] = fmaf(vc[c], w1.z, acc[6]);
                acc[7] = fmaf(vc[c], w1.w, acc[7]);
            }
        }
        // ---- key projection: c in [64, 128) ----
#pragma unroll
        for (int cb = 0; cb < C / 4; ++cb) {
            const float4 v = k4[cb];
            const float4* wp = reinterpret_cast<const float4*>(&Ws[(C + cb * 4) * H]);
            const float vc[4] = {v.x, v.y, v.z, v.w};
#pragma unroll
            for (int c = 0; c < 4; ++c) {
                const float4 w0 = wp[c * 2 + 0];
                const float4 w1 = wp[c * 2 + 1];
                acc[0] = fmaf(vc[c], w0.x, acc[0]);
                acc[1] = fmaf(vc[c], w0.y, acc[1]);
                acc[2] = fmaf(vc[c], w0.z, acc[2]);
                acc[3] = fmaf(vc[c], w0.w, acc[3]);
                acc[4] = fmaf(vc[c], w1.x, acc[4]);
                acc[5] = fmaf(vc[c], w1.y, acc[5]);
                acc[6] = fmaf(vc[c], w1.z, acc[6]);
                acc[7] = fmaf(vc[c], w1.w, acc[7]);
            }
        }

        const float r = roi[(size_t)bm * N + n];
#pragma unroll
        for (int h = 0; h < H; ++h) {
            const float e = __expf(acc[h]) * r;
            attn[j][h] = e;
            sums[h] += e;
        }
    }

    // ---- reduce sums over the 512 n-values of this (b,m) row ----
    // 1) butterfly within warp
#pragma unroll
    for (int h = 0; h < H; ++h) {
        float s = sums[h];
#pragma unroll
        for (int off = 16; off > 0; off >>= 1)
            s += __shfl_xor_sync(0xffffffffu, s, off);
        sums[h] = s;
    }
    const int warp = tid >> 5;
    const int lane = tid & 31;
    if (lane < H) wsum[warp][lane] = sums[lane];
    __syncthreads();

    float inv[H];
#pragma unroll
    for (int h = 0; h < H; ++h) {
        float t = 0.f;
#pragma unroll
        for (int w = 0; w < 8; ++w) t += wsum[w][h];
        inv[h] = 1.0f / t;
    }

    // ---- normalize + coalesced store (8 floats = two float4 per n) ----
#pragma unroll
    for (int j = 0; j < 2; ++j) {
        const int n = tid + j * THREADS;
        float4* o4 = reinterpret_cast<float4*>(out + ((size_t)bm * N + n) * H);
        float4 a, b2;
        a.x  = attn[j][0] * inv[0];
        a.y  = attn[j][1] * inv[1];
        a.z  = attn[j][2] * inv[2];
        a.w  = attn[j][3] * inv[3];
        b2.x = attn[j][4] * inv[4];
        b2.y = attn[j][5] * inv[5];
        b2.z = attn[j][6] * inv[6];
        b2.w = attn[j][7] * inv[7];
        o4[0] = a;
        o4[1] = b2;
    }
}

} // namespace

extern "C" void kernel_launch(void* const* d_in, const int* in_sizes, int n_in,
                              void* d_out, int out_size)
{
    const float* q    = (const float*)d_in[0];
    const float* k    = (const float*)d_in[1];
    const float* roi  = (const float*)d_in[2];
    const float* W    = (const float*)d_in[3];
    const float* bias = (const float*)d_in[4];
    float* out        = (float*)d_out;

    (void)in_sizes; (void)n_in; (void)out_size;

    dim3 grid(B * N);   // one block per (b, m) row
    dim3 block(THREADS);
    mha_fused_kernel<<<grid, block>>>(q, k, roi, W, bias, out);
}